// round 15
// baseline (speedup 1.0000x reference)
#include <cuda_runtime.h>
#include <cuda_fp16.h>
#include <stdint.h>

// ---------------------------------------------------------------------------
// Multihead_Attention b=4, n=4096, d=512, inner=512
// R15: numerics reverted to fp16 (R12, verified 8.4e-5). QK^T and PV move to
//      gemm_pf: 1 CTA/SM, 4-stage cp.async, CUTLASS-style rolling ks-fragment
//      prefetch (double-buffered ah/bh) to kill ldsm->mma RAW stalls that the
//      cycle model shows are the missing ~34%. Projections keep the proven
//      2-CTA/SM R12 kernel.
// ---------------------------------------------------------------------------

#define BATCH 4
#define SEQ   4096
#define DIM   512
#define MTOT  (BATCH * SEQ)

#define BM 128
#define BN 128
#define NPARTS 128   // (SEQ/BN)=32 x-blocks * 4 warpN partials

// scratch (fp16 storage as uint16)
__device__ uint16_t g_x16[(size_t)MTOT * DIM];
__device__ uint16_t g_y16[(size_t)MTOT * DIM];
__device__ uint16_t g_wqk16[2 * DIM * DIM];             // Wq rows 0-511, Wk 512-1023
__device__ uint16_t g_wv16[DIM * DIM];
__device__ uint16_t g_wo16[DIM * DIM];
__device__ uint16_t g_qk16[(size_t)MTOT * 2 * DIM];     // fused q|k, ld=1024
__device__ uint16_t g_vt [(size_t)BATCH * DIM * SEQ];   // V^T per batch [512,4096]
__device__ uint16_t g_p  [(size_t)BATCH * SEQ * SEQ];   // 2^(scaled logits), fp16
__device__ float    g_rpart[(size_t)NPARTS * MTOT];
__device__ float    g_rsum[MTOT];
__device__ uint16_t g_c16[(size_t)MTOT * DIM];

// ---------------- helpers ---------------------------------------------------

__device__ __forceinline__ uint32_t smem_u32(const void* p) {
    uint32_t a;
    asm("{ .reg .u64 t; cvta.to.shared.u64 t, %1; cvt.u32.u64 %0, t; }"
        : "=r"(a) : "l"(p));
    return a;
}

__device__ __forceinline__ void ldsm4(uint32_t& r0, uint32_t& r1,
                                      uint32_t& r2, uint32_t& r3, uint32_t a) {
    asm volatile("ldmatrix.sync.aligned.m8n8.x4.shared.b16 {%0,%1,%2,%3}, [%4];"
                 : "=r"(r0), "=r"(r1), "=r"(r2), "=r"(r3) : "r"(a));
}

__device__ __forceinline__ void mma_f16(float* d, const uint32_t* a,
                                        const uint32_t* b) {
    asm volatile(
        "mma.sync.aligned.m16n8k16.row.col.f32.f16.f16.f32 "
        "{%0,%1,%2,%3}, {%4,%5,%6,%7}, {%8,%9}, {%0,%1,%2,%3};"
        : "+f"(d[0]), "+f"(d[1]), "+f"(d[2]), "+f"(d[3])
        : "r"(a[0]), "r"(a[1]), "r"(a[2]), "r"(a[3]), "r"(b[0]), "r"(b[1]));
}

#define CP16(dst, src) \
    asm volatile("cp.async.cg.shared.global [%0], [%1], 16;" \
                 :: "r"(dst), "l"(src) : "memory")
#define CP_COMMIT() asm volatile("cp.async.commit_group;" ::: "memory")
#define CP_WAIT2()  asm volatile("cp.async.wait_group 2;" ::: "memory")
#define CP_WAIT1()  asm volatile("cp.async.wait_group 1;" ::: "memory")
#define CP_WAIT0()  asm volatile("cp.async.wait_group 0;" ::: "memory")

__device__ __forceinline__ void st_f16x2(uint16_t* H, size_t idx,
                                         float v0, float v1) {
    __half2 h = __floats2half2_rn(v0, v1);
    *(uint32_t*)(H + idx) = *(uint32_t*)&h;
}

// f16x2 exp2: one MUFU op for two values
__device__ __forceinline__ uint32_t ex2_f16x2(float x0, float x1) {
    __half2 hx = __floats2half2_rn(x0, x1);
    uint32_t hin = *(uint32_t*)&hx;
    uint32_t hout;
    asm volatile("ex2.approx.f16x2 %0, %1;" : "=r"(hout) : "r"(hin));
    return hout;
}

// ---------------- shared tile constants ---------------------------------------
// f16, BK=64 elems (128B rows), SW128 swizzle (seg ^ row&7).
#define TS_STRIDE 132
#define A_OFF  0u
#define B_OFF  16384u
#define STAGE  32768u
#define SMEM_MAIN (3 * 32768)   //  98304 (2-CTA kernel, 3 stages)
#define SMEM_PF   (4 * 32768)   // 131072 (1-CTA prefetch kernel, 4 stages)

// ---------------- GEMM (R12, 2 CTAs/SM) — projections --------------------------
// C = A[M,K](f16,lda) @ B[N,K]^T(f16,ldb), fp32 accum. CTA 128x128, warp 64x32.
// OUT: 0 = fp32 * alpha + bias(aux); 2 = f16 (ldc); 3 = f16 transposed.

template <int OUT>
__global__ __launch_bounds__(256, 2) void gemm(
    const uint16_t* __restrict__ A, const uint16_t* __restrict__ B,
    int K, int lda, int ldb, long sA, long sB,
    float* __restrict__ Cf, uint16_t* __restrict__ Ch,
    int ldc, long sC, float alpha,
    const float* __restrict__ aux, long sAux)
{
    extern __shared__ char smem[];
    const uint32_t sb = smem_u32(smem);
    const int t = threadIdx.x, lane = t & 31, wid = t >> 5;
    const int warpM = wid & 1;
    const int warpN = wid >> 1;

    const int bz = blockIdx.z;
    A += bz * sA; B += bz * sB;
    const int m0 = blockIdx.y * BM, n0 = blockIdx.x * BN;

    const int seg = t & 7;
    const int r0  = t >> 3;
    const uint32_t dA = (uint32_t)r0 * 128u
                      + (((uint32_t)seg ^ ((uint32_t)r0 & 7u)) << 4);
    const long rowStepA = (long)32 * lda;
    const long rowStepB = (long)32 * ldb;

    const uint16_t* srcA = A + (long)(m0 + r0) * lda + seg * 8;
    const uint16_t* srcB = B + (long)(n0 + r0) * ldb + seg * 8;

    const int arow_o = warpM * 64 + (lane & 7) + ((lane >> 3) & 1) * 8;
    const int asegh  = lane >> 4;
    const int brow_o = warpN * 32 + (lane & 7) + (lane >> 4) * 8;
    const int bsegh  = (lane >> 3) & 1;

    uint32_t ar128[4], axr[4];
#pragma unroll
    for (int mt = 0; mt < 4; mt++) {
        int r = arow_o + mt * 16;
        ar128[mt] = (uint32_t)(r * 128);
        axr[mt]   = (uint32_t)(r & 7);
    }
    uint32_t br128[2], bxr[2];
#pragma unroll
    for (int np = 0; np < 2; np++) {
        int r = brow_o + np * 16;
        br128[np] = (uint32_t)(r * 128);
        bxr[np]   = (uint32_t)(r & 7);
    }

    float acc[4][4][4];
#pragma unroll
    for (int i = 0; i < 4; i++)
#pragma unroll
        for (int j = 0; j < 4; j++)
#pragma unroll
            for (int k = 0; k < 4; k++) acc[i][j][k] = 0.0f;

    const int nch = K >> 6;

    auto issue = [&](int c, int st) {
        const uint32_t base = sb + (uint32_t)st * STAGE;
        const uint16_t* pa = srcA + c * 64;
        const uint16_t* pb = srcB + c * 64;
#pragma unroll
        for (int i = 0; i < 4; i++) {
            CP16(base + A_OFF + dA + i * 4096u, pa + i * rowStepA);
            CP16(base + B_OFF + dA + i * 4096u, pb + i * rowStepB);
        }
        CP_COMMIT();
    };

    issue(0, 0);
    issue(1, 1);

    int st = 0;
    for (int c = 0; c < nch; c++) {
        CP_WAIT1();
        __syncthreads();
        if (c + 2 < nch) {
            int stn = st + 2; if (stn >= 3) stn -= 3;
            issue(c + 2, stn);
        }

        const uint32_t Sa = sb + (uint32_t)st * STAGE;
#pragma unroll
        for (int ks = 0; ks < 4; ks++) {
            uint32_t ah[4][4];
#pragma unroll
            for (int mt = 0; mt < 4; mt++) {
                uint32_t sg = (uint32_t)(ks * 2 + asegh);
                uint32_t off = ar128[mt] + ((sg ^ axr[mt]) << 4);
                ldsm4(ah[mt][0], ah[mt][1], ah[mt][2], ah[mt][3], Sa + A_OFF + off);
            }
            uint32_t bh[4][2];
#pragma unroll
            for (int np = 0; np < 2; np++) {
                uint32_t sg = (uint32_t)(ks * 2 + bsegh);
                uint32_t off = br128[np] + ((sg ^ bxr[np]) << 4);
                uint32_t q0, q1, q2, q3;
                ldsm4(q0, q1, q2, q3, Sa + B_OFF + off);
                bh[np * 2][0] = q0; bh[np * 2][1] = q1;
                bh[np * 2 + 1][0] = q2; bh[np * 2 + 1][1] = q3;
            }
#pragma unroll
            for (int mt = 0; mt < 4; mt++)
#pragma unroll
                for (int nt = 0; nt < 4; nt++)
                    mma_f16(acc[mt][nt], ah[mt], bh[nt]);
        }
        st++; if (st >= 3) st = 0;
    }
    CP_WAIT0();

    // ---------------- epilogue ----------------
    if (OUT == 3) {
        __syncthreads();
        float* ts = (float*)smem;  // [128][TS_STRIDE]
        uint16_t* Co = Ch + bz * sC;
#pragma unroll
        for (int mt = 0; mt < 4; mt++) {
            const int rl = warpM * 64 + mt * 16 + (lane >> 2);
#pragma unroll
            for (int nt = 0; nt < 4; nt++) {
                const int cl = warpN * 32 + nt * 8 + (lane & 3) * 2;
                ts[cl * TS_STRIDE + rl]           = acc[mt][nt][0];
                ts[(cl + 1) * TS_STRIDE + rl]     = acc[mt][nt][1];
                ts[cl * TS_STRIDE + rl + 8]       = acc[mt][nt][2];
                ts[(cl + 1) * TS_STRIDE + rl + 8] = acc[mt][nt][3];
            }
        }
        __syncthreads();
        const int nr = t >> 1;
        const int mh = (t & 1) * 64;
        const float* src = ts + nr * TS_STRIDE + mh;
        const size_t rowb = (size_t)(n0 + nr) * ldc + m0 + mh;
#pragma unroll
        for (int i = 0; i < 64; i += 2)
            st_f16x2(Co, rowb + i, src[i], src[i + 1]);
        return;
    }

    float* Cfo = (OUT == 0) ? (Cf + bz * sC) : nullptr;
    uint16_t* Cho = (OUT != 0) ? (Ch + bz * sC) : nullptr;

#pragma unroll
    for (int mt = 0; mt < 4; mt++) {
        const int r0i = m0 + warpM * 64 + mt * 16 + (lane >> 2);
#pragma unroll
        for (int nt = 0; nt < 4; nt++) {
            const int col = n0 + warpN * 32 + nt * 8 + (lane & 3) * 2;
            const size_t i0 = (size_t)r0i * ldc + col;
            const size_t i1 = (size_t)(r0i + 8) * ldc + col;
            float v0 = acc[mt][nt][0], v1 = acc[mt][nt][1];
            float v2 = acc[mt][nt][2], v3 = acc[mt][nt][3];
            if (OUT == 0) {
                float b0 = aux ? aux[col] : 0.0f;
                float b1 = aux ? aux[col + 1] : 0.0f;
                *(float2*)&Cfo[i0] = make_float2(v0 * alpha + b0, v1 * alpha + b1);
                *(float2*)&Cfo[i1] = make_float2(v2 * alpha + b0, v3 * alpha + b1);
            } else {   // OUT == 2
                st_f16x2(Cho, i0, v0, v1);
                st_f16x2(Cho, i1, v2, v3);
            }
        }
    }
}

// ---------------- GEMM_PF (1 CTA/SM, 4 stages, rolling ks prefetch) ------------
// Used for QK^T (OUT=5) and PV (OUT=6).

template <int OUT>
__global__ __launch_bounds__(256, 1) void gemm_pf(
    const uint16_t* __restrict__ A, const uint16_t* __restrict__ B,
    int K, int lda, int ldb, long sA, long sB,
    float* __restrict__ Cf, uint16_t* __restrict__ Ch,
    int ldc, long sC, float alpha,
    const float* __restrict__ aux, long sAux)
{
    extern __shared__ char smem[];
    const uint32_t sb = smem_u32(smem);
    const int t = threadIdx.x, lane = t & 31, wid = t >> 5;
    const int warpM = wid & 1;
    const int warpN = wid >> 1;

    const int bz = blockIdx.z;
    A += bz * sA; B += bz * sB;
    const int m0 = blockIdx.y * BM, n0 = blockIdx.x * BN;

    const int seg = t & 7;
    const int r0  = t >> 3;
    const uint32_t dA = (uint32_t)r0 * 128u
                      + (((uint32_t)seg ^ ((uint32_t)r0 & 7u)) << 4);
    const long rowStepA = (long)32 * lda;
    const long rowStepB = (long)32 * ldb;

    const uint16_t* srcA = A + (long)(m0 + r0) * lda + seg * 8;
    const uint16_t* srcB = B + (long)(n0 + r0) * ldb + seg * 8;

    const int arow_o = warpM * 64 + (lane & 7) + ((lane >> 3) & 1) * 8;
    const int asegh  = lane >> 4;
    const int brow_o = warpN * 32 + (lane & 7) + (lane >> 4) * 8;
    const int bsegh  = (lane >> 3) & 1;

    uint32_t ar128[4], axr[4];
#pragma unroll
    for (int mt = 0; mt < 4; mt++) {
        int r = arow_o + mt * 16;
        ar128[mt] = (uint32_t)(r * 128);
        axr[mt]   = (uint32_t)(r & 7);
    }
    uint32_t br128[2], bxr[2];
#pragma unroll
    for (int np = 0; np < 2; np++) {
        int r = brow_o + np * 16;
        br128[np] = (uint32_t)(r * 128);
        bxr[np]   = (uint32_t)(r & 7);
    }

    float acc[4][4][4];
#pragma unroll
    for (int i = 0; i < 4; i++)
#pragma unroll
        for (int j = 0; j < 4; j++)
#pragma unroll
            for (int k = 0; k < 4; k++) acc[i][j][k] = 0.0f;

    const int nch = K >> 6;

    auto issue = [&](int c, int st) {
        const uint32_t base = sb + (uint32_t)st * STAGE;
        const uint16_t* pa = srcA + c * 64;
        const uint16_t* pb = srcB + c * 64;
#pragma unroll
        for (int i = 0; i < 4; i++) {
            CP16(base + A_OFF + dA + i * 4096u, pa + i * rowStepA);
            CP16(base + B_OFF + dA + i * 4096u, pb + i * rowStepB);
        }
        CP_COMMIT();
    };

    issue(0, 0);
    issue(1, 1);
    issue(2, 2);

    // fragment double buffers
    uint32_t ah[2][4][4];
    uint32_t bh[2][4][2];

    auto loadA = [&](uint32_t Sa, int ks, int buf) {
#pragma unroll
        for (int mt = 0; mt < 4; mt++) {
            uint32_t sg = (uint32_t)(ks * 2 + asegh);
            uint32_t off = ar128[mt] + ((sg ^ axr[mt]) << 4);
            ldsm4(ah[buf][mt][0], ah[buf][mt][1], ah[buf][mt][2], ah[buf][mt][3],
                  Sa + A_OFF + off);
        }
    };
    auto loadB = [&](uint32_t Sa, int ks, int buf) {
#pragma unroll
        for (int np = 0; np < 2; np++) {
            uint32_t sg = (uint32_t)(ks * 2 + bsegh);
            uint32_t off = br128[np] + ((sg ^ bxr[np]) << 4);
            uint32_t q0, q1, q2, q3;
            ldsm4(q0, q1, q2, q3, Sa + B_OFF + off);
            bh[buf][np * 2][0] = q0; bh[buf][np * 2][1] = q1;
            bh[buf][np * 2 + 1][0] = q2; bh[buf][np * 2 + 1][1] = q3;
        }
    };

    int st = 0;
    for (int c = 0; c < nch; c++) {
        CP_WAIT2();
        __syncthreads();

        const uint32_t Sa = sb + (uint32_t)st * STAGE;

        // load ks=0 fragments, then kick off next stage's cp.async
        loadA(Sa, 0, 0);
        loadB(Sa, 0, 0);
        if (c + 3 < nch) {
            int stn = st + 3; if (stn >= 4) stn -= 4;
            issue(c + 3, stn);
        }

#pragma unroll
        for (int ks = 0; ks < 4; ks++) {
            const int cur = ks & 1;
            const int nxt = cur ^ 1;
            if (ks < 3) {            // rolling prefetch of ks+1
                loadA(Sa, ks + 1, nxt);
                loadB(Sa, ks + 1, nxt);
            }
#pragma unroll
            for (int mt = 0; mt < 4; mt++)
#pragma unroll
                for (int nt = 0; nt < 4; nt++)
                    mma_f16(acc[mt][nt], ah[cur][mt], bh[cur][nt]);
        }
        st++; if (st >= 4) st = 0;
    }
    CP_WAIT0();

    // ---------------- epilogue ----------------
    uint16_t* Cho = Ch + bz * sC;

#pragma unroll
    for (int mt = 0; mt < 4; mt++) {
        const int r0i = m0 + warpM * 64 + mt * 16 + (lane >> 2);
        float inv0 = 1.0f, inv1 = 1.0f;
        if (OUT == 6) {
            inv0 = 1.0f / aux[bz * sAux + r0i];
            inv1 = 1.0f / aux[bz * sAux + r0i + 8];
        }
        __half2 hs0 = __floats2half2_rn(0.0f, 0.0f);
        __half2 hs1 = __floats2half2_rn(0.0f, 0.0f);
#pragma unroll
        for (int nt = 0; nt < 4; nt++) {
            const int col = n0 + warpN * 32 + nt * 8 + (lane & 3) * 2;
            const size_t i0 = (size_t)r0i * ldc + col;
            const size_t i1 = (size_t)(r0i + 8) * ldc + col;
            float v0 = acc[mt][nt][0], v1 = acc[mt][nt][1];
            float v2 = acc[mt][nt][2], v3 = acc[mt][nt][3];
            if (OUT == 5) {
                uint32_t e01 = ex2_f16x2(alpha * v0, alpha * v1);
                uint32_t e23 = ex2_f16x2(alpha * v2, alpha * v3);
                *(uint32_t*)(Cho + i0) = e01;
                *(uint32_t*)(Cho + i1) = e23;
                hs0 = __hadd2(hs0, *(__half2*)&e01);
                hs1 = __hadd2(hs1, *(__half2*)&e23);
            } else {   // OUT == 6
                st_f16x2(Cho, i0, v0 * inv0, v1 * inv0);
                st_f16x2(Cho, i1, v2 * inv1, v3 * inv1);
            }
        }
        if (OUT == 5) {
            float s0 = __low2float(hs0) + __high2float(hs0);
            float s1 = __low2float(hs1) + __high2float(hs1);
            s0 += __shfl_xor_sync(0xffffffffu, s0, 1);
            s0 += __shfl_xor_sync(0xffffffffu, s0, 2);
            s1 += __shfl_xor_sync(0xffffffffu, s1, 1);
            s1 += __shfl_xor_sync(0xffffffffu, s1, 2);
            if ((lane & 3) == 0) {
                float* part = Cf + ((size_t)blockIdx.x * 4 + warpN) * MTOT
                                 + bz * sAux;
                part[r0i]     = s0;
                part[r0i + 8] = s1;
            }
        }
    }
}

// ---------------- converts ----------------------------------------------------

__global__ void convert_xy(const float4* __restrict__ x,
                           const float4* __restrict__ y,
                           uint32_t* __restrict__ xd,
                           uint32_t* __restrict__ yd, long n4)
{
    long i = (long)blockIdx.x * blockDim.x + threadIdx.x;
    const long stride = (long)gridDim.x * blockDim.x;
    for (; i < 2 * n4; i += stride) {
        const bool isY = (i >= n4);
        long j = isY ? i - n4 : i;
        float4 f = (isY ? y : x)[j];
        uint32_t* d = isY ? yd : xd;
        __half2 h0 = __floats2half2_rn(f.x, f.y);
        __half2 h1 = __floats2half2_rn(f.z, f.w);
        d[j * 2 + 0] = *(uint32_t*)&h0;
        d[j * 2 + 1] = *(uint32_t*)&h1;
    }
}

__global__ void convert_w4(const float4* __restrict__ wq,
                           const float4* __restrict__ wk,
                           const float4* __restrict__ wv,
                           const float4* __restrict__ wo,
                           uint32_t* __restrict__ wqk,
                           uint32_t* __restrict__ wvd,
                           uint32_t* __restrict__ wod)
{
    const long n4 = (long)DIM * DIM / 4;
    long i = (long)blockIdx.x * blockDim.x + threadIdx.x;
    const long stride = (long)gridDim.x * blockDim.x;
    for (; i < 4 * n4; i += stride) {
        int which = (int)(i / n4);
        long j = i - (long)which * n4;
        const float4* s = (which == 0) ? wq : (which == 1) ? wk
                        : (which == 2) ? wv : wo;
        uint32_t* d = (which == 0) ? wqk : (which == 1) ? (wqk + 2 * n4)
                    : (which == 2) ? wvd : wod;
        float4 f = s[j];
        __half2 h0 = __floats2half2_rn(f.x, f.y);
        __half2 h1 = __floats2half2_rn(f.z, f.w);
        d[j * 2 + 0] = *(uint32_t*)&h0;
        d[j * 2 + 1] = *(uint32_t*)&h1;
    }
}

// ---------------- fold per-(xblock,warpN) row-sum partials --------------------

__global__ __launch_bounds__(256) void reduce_rsum(
    const float* __restrict__ part, float* __restrict__ rsum)
{
    const int row = blockIdx.x * 256 + threadIdx.x;
    float s = 0.0f;
#pragma unroll 16
    for (int x = 0; x < NPARTS; x++)
        s += part[(size_t)x * MTOT + row];
    rsum[row] = s;
}

// ---------------- launch ------------------------------------------------------

extern "C" void kernel_launch(void* const* d_in, const int* in_sizes, int n_in,
                              void* d_out, int out_size)
{
    const float* x  = (const float*)d_in[0];
    const float* y  = (const float*)d_in[1];
    const float* Wq = (const float*)d_in[2];
    const float* Wk = (const float*)d_in[3];
    const float* Wv = (const float*)d_in[4];
    const float* Wo = (const float*)d_in[5];
    const float* bo = (const float*)d_in[6];
    float* out = (float*)d_out;

    auto sym = [](const void* s) {
        void* p = nullptr;
        cudaGetSymbolAddress(&p, (const void*)s);
        return p;
    };
    uint16_t* x16   = (uint16_t*)sym(g_x16);
    uint16_t* y16   = (uint16_t*)sym(g_y16);
    uint16_t* wqk16 = (uint16_t*)sym(g_wqk16);
    uint16_t* wv16  = (uint16_t*)sym(g_wv16);
    uint16_t* wo16  = (uint16_t*)sym(g_wo16);
    uint16_t* qk16  = (uint16_t*)sym(g_qk16);
    uint16_t* vt    = (uint16_t*)sym(g_vt);
    uint16_t* p     = (uint16_t*)sym(g_p);
    float*    rp    = (float*)sym(g_rpart);
    float*    rs    = (float*)sym(g_rsum);
    uint16_t* c16   = (uint16_t*)sym(g_c16);

    cudaFuncSetAttribute(gemm<0>, cudaFuncAttributeMaxDynamicSharedMemorySize, SMEM_MAIN);
    cudaFuncSetAttribute(gemm<2>, cudaFuncAttributeMaxDynamicSharedMemorySize, SMEM_MAIN);
    cudaFuncSetAttribute(gemm<3>, cudaFuncAttributeMaxDynamicSharedMemorySize, SMEM_MAIN);
    cudaFuncSetAttribute(gemm_pf<5>, cudaFuncAttributeMaxDynamicSharedMemorySize, SMEM_PF);
    cudaFuncSetAttribute(gemm_pf<6>, cudaFuncAttributeMaxDynamicSharedMemorySize, SMEM_PF);

    const float SCALE = 0.044194173824159216f;               // 1/sqrt(512)
    const float SCALE_LOG2E = SCALE * 1.4426950408889634f;   // fold log2(e)

    const long nXY4 = (long)MTOT * DIM / 4;

    // 0) convert inputs (x + y fused)
    convert_xy<<<4096, 256>>>((const float4*)x, (const float4*)y,
                              (uint32_t*)x16, (uint32_t*)y16, nXY4);
    // 1) convert all 4 weights (Wq|Wk concatenated)
    convert_w4<<<1024, 256>>>((const float4*)Wq, (const float4*)Wk,
                              (const float4*)Wv, (const float4*)Wo,
                              (uint32_t*)wqk16, (uint32_t*)wv16, (uint32_t*)wo16);

    // 2) fused Q|K projection: [16384,1024] = x16 @ Wqk^T  -> qk16 (ldc=1024)
    {
        dim3 grid(2 * DIM / BN, MTOT / BM, 1);
        gemm<2><<<grid, 256, SMEM_MAIN>>>(x16, wqk16, DIM, DIM, DIM, 0, 0,
                                          nullptr, qk16, 2 * DIM, 0,
                                          1.0f, nullptr, 0);
    }
    // 3) P_unnorm = 2^(SCALE_LOG2E * Q @ K^T) + row-sum partials  [profile target]
    {
        dim3 grid(SEQ / BN, SEQ / BM, BATCH);
        gemm_pf<5><<<grid, 256, SMEM_PF>>>(qk16, qk16 + DIM, DIM,
                                           2 * DIM, 2 * DIM,
                                           (long)SEQ * 2 * DIM, (long)SEQ * 2 * DIM,
                                           rp, p, SEQ,
                                           (long)SEQ * SEQ, SCALE_LOG2E, nullptr, SEQ);
    }
    // 4) V projection -> fp16 transposed per batch: vt[b][d][seq]
    {
        dim3 grid(DIM / BN, SEQ / BM, BATCH);
        gemm<3><<<grid, 256, SMEM_MAIN>>>(y16, wv16, DIM, DIM, DIM,
                                          (long)SEQ * DIM, 0,
                                          nullptr, vt, SEQ,
                                          (long)DIM * SEQ, 1.0f, nullptr, 0);
    }
    // 5) fold row-sum partials
    reduce_rsum<<<MTOT / 256, 256>>>(rp, rs);
    // 6) Context: C = (P @ V) / rowsum -> fp16
    {
        dim3 grid(DIM / BN, SEQ / BM, BATCH);
        gemm_pf<6><<<grid, 256, SMEM_PF>>>(p, vt, SEQ, SEQ, SEQ,
                                           (long)SEQ * SEQ, (long)DIM * SEQ,
                                           nullptr, c16, DIM,
                                           (long)SEQ * DIM, 1.0f, rs, SEQ);
    }
    // 7) Output projection + bias -> fp32
    {
        dim3 grid(DIM / BN, MTOT / BM, 1);
        gemm<0><<<grid, 256, SMEM_MAIN>>>(c16, wo16, DIM, DIM, DIM, 0, 0,
                                          out, nullptr, DIM, 0, 1.0f, bo, 0);
    }
}

// round 16
// speedup vs baseline: 1.1706x; 1.1706x over previous
#include <cuda_runtime.h>
#include <cuda_fp16.h>
#include <stdint.h>

// ---------------------------------------------------------------------------
// Multihead_Attention b=4, n=4096, d=512, inner=512
// R16: R12 (verified 501us) + warp ks-phase staggering: warp w walks the 4
//      ks-steps of each chunk in rotated order ((i+wid)&3), breaking the
//      post-barrier phase-lock that made the smem and tensor pipes alternate
//      (63% + 67%) instead of overlap.
// ---------------------------------------------------------------------------

#define BATCH 4
#define SEQ   4096
#define DIM   512
#define MTOT  (BATCH * SEQ)

#define BM 128
#define BN 128
#define NPARTS 128   // (SEQ/BN)=32 x-blocks * 4 warpN partials

// scratch (fp16 storage as uint16)
__device__ uint16_t g_x16[(size_t)MTOT * DIM];
__device__ uint16_t g_y16[(size_t)MTOT * DIM];
__device__ uint16_t g_wqk16[2 * DIM * DIM];             // Wq rows 0-511, Wk 512-1023
__device__ uint16_t g_wv16[DIM * DIM];
__device__ uint16_t g_wo16[DIM * DIM];
__device__ uint16_t g_qk16[(size_t)MTOT * 2 * DIM];     // fused q|k, ld=1024
__device__ uint16_t g_vt [(size_t)BATCH * DIM * SEQ];   // V^T per batch [512,4096]
__device__ uint16_t g_p  [(size_t)BATCH * SEQ * SEQ];   // 2^(scaled logits), fp16
__device__ float    g_rpart[(size_t)NPARTS * MTOT];
__device__ float    g_rsum[MTOT];
__device__ uint16_t g_c16[(size_t)MTOT * DIM];

// ---------------- helpers ---------------------------------------------------

__device__ __forceinline__ uint32_t smem_u32(const void* p) {
    uint32_t a;
    asm("{ .reg .u64 t; cvta.to.shared.u64 t, %1; cvt.u32.u64 %0, t; }"
        : "=r"(a) : "l"(p));
    return a;
}

__device__ __forceinline__ void ldsm4(uint32_t& r0, uint32_t& r1,
                                      uint32_t& r2, uint32_t& r3, uint32_t a) {
    asm volatile("ldmatrix.sync.aligned.m8n8.x4.shared.b16 {%0,%1,%2,%3}, [%4];"
                 : "=r"(r0), "=r"(r1), "=r"(r2), "=r"(r3) : "r"(a));
}

__device__ __forceinline__ void mma_f16(float* d, const uint32_t* a,
                                        const uint32_t* b) {
    asm volatile(
        "mma.sync.aligned.m16n8k16.row.col.f32.f16.f16.f32 "
        "{%0,%1,%2,%3}, {%4,%5,%6,%7}, {%8,%9}, {%0,%1,%2,%3};"
        : "+f"(d[0]), "+f"(d[1]), "+f"(d[2]), "+f"(d[3])
        : "r"(a[0]), "r"(a[1]), "r"(a[2]), "r"(a[3]), "r"(b[0]), "r"(b[1]));
}

#define CP16(dst, src) \
    asm volatile("cp.async.cg.shared.global [%0], [%1], 16;" \
                 :: "r"(dst), "l"(src) : "memory")
#define CP_COMMIT() asm volatile("cp.async.commit_group;" ::: "memory")
#define CP_WAIT1()  asm volatile("cp.async.wait_group 1;" ::: "memory")
#define CP_WAIT0()  asm volatile("cp.async.wait_group 0;" ::: "memory")

__device__ __forceinline__ void st_f16x2(uint16_t* H, size_t idx,
                                         float v0, float v1) {
    __half2 h = __floats2half2_rn(v0, v1);
    *(uint32_t*)(H + idx) = *(uint32_t*)&h;
}

// f16x2 exp2: one MUFU op for two values
__device__ __forceinline__ uint32_t ex2_f16x2(float x0, float x1) {
    __half2 hx = __floats2half2_rn(x0, x1);
    uint32_t hin = *(uint32_t*)&hx;
    uint32_t hout;
    asm volatile("ex2.approx.f16x2 %0, %1;" : "=r"(hout) : "r"(hin));
    return hout;
}

// ---------------- GEMM -------------------------------------------------------
// C = A[M,K](f16, lda) @ B[N,K]^T(f16, ldb), fp32 accum. CTA 128x128, warp 64x32.
// BK=64: 128B smem rows, SW128 swizzle (seg ^ row&7). 2 CTAs/SM.
// Warps walk ks in rotated order ((i+wid)&3) to overlap smem & tensor pipes.
// OUT: 0 = fp32 * alpha + bias(aux)
//      2 = f16 (ldc)
//      3 = f16 transposed (C[n*ldc+m]) via smem staging
//      5 = f16 of 2^(alpha*acc); + per-(xblock,warpN) row-sum partials
//      6 = f16 of acc / aux[bz*sAux + row]

#define TS_STRIDE 132
#define STAGES 3
#define A_OFF  0u
#define B_OFF  16384u
#define STAGE  32768u
#define SMEM_MAIN (STAGES * 32768)            // 98304

template <int OUT>
__global__ __launch_bounds__(256, 2) void gemm(
    const uint16_t* __restrict__ A, const uint16_t* __restrict__ B,
    int K, int lda, int ldb, long sA, long sB,
    float* __restrict__ Cf, uint16_t* __restrict__ Ch,
    int ldc, long sC, float alpha,
    const float* __restrict__ aux, long sAux)
{
    extern __shared__ char smem[];
    const uint32_t sb = smem_u32(smem);
    const int t = threadIdx.x, lane = t & 31, wid = t >> 5;
    const int warpM = wid & 1;        // 2 x 64 rows
    const int warpN = wid >> 1;       // 4 x 32 cols

    const int bz = blockIdx.z;
    A += bz * sA; B += bz * sB;
    const int m0 = blockIdx.y * BM, n0 = blockIdx.x * BN;

    // cp.async mapping: 128B rows, 8 segs of 16B; thread -> (row r0+32i, seg)
    const int seg = t & 7;
    const int r0  = t >> 3;                    // 0..31
    const uint32_t dA = (uint32_t)r0 * 128u
                      + (((uint32_t)seg ^ ((uint32_t)r0 & 7u)) << 4);
    const long rowStepA = (long)32 * lda;
    const long rowStepB = (long)32 * ldb;

    const uint16_t* srcA = A + (long)(m0 + r0) * lda + seg * 8;
    const uint16_t* srcB = B + (long)(n0 + r0) * ldb + seg * 8;

    // ldmatrix components
    const int arow_o = warpM * 64 + (lane & 7) + ((lane >> 3) & 1) * 8;
    const int asegh  = lane >> 4;              // 0/1
    const int brow_o = warpN * 32 + (lane & 7) + (lane >> 4) * 8;
    const int bsegh  = (lane >> 3) & 1;        // 0/1

    uint32_t ar128[4], axr[4];
#pragma unroll
    for (int mt = 0; mt < 4; mt++) {
        int r = arow_o + mt * 16;
        ar128[mt] = (uint32_t)(r * 128);
        axr[mt]   = (uint32_t)(r & 7);
    }
    uint32_t br128[2], bxr[2];
#pragma unroll
    for (int np = 0; np < 2; np++) {
        int r = brow_o + np * 16;
        br128[np] = (uint32_t)(r * 128);
        bxr[np]   = (uint32_t)(r & 7);
    }

    float acc[4][4][4];
#pragma unroll
    for (int i = 0; i < 4; i++)
#pragma unroll
        for (int j = 0; j < 4; j++)
#pragma unroll
            for (int k = 0; k < 4; k++) acc[i][j][k] = 0.0f;

    const int nch = K >> 6;
    const int ksoff = wid & 3;     // per-warp ks phase

    auto issue = [&](int c, int st) {
        const uint32_t base = sb + (uint32_t)st * STAGE;
        const uint16_t* pa = srcA + c * 64;
        const uint16_t* pb = srcB + c * 64;
#pragma unroll
        for (int i = 0; i < 4; i++) {
            CP16(base + A_OFF + dA + i * 4096u, pa + i * rowStepA);
            CP16(base + B_OFF + dA + i * 4096u, pb + i * rowStepB);
        }
        CP_COMMIT();
    };

    issue(0, 0);
    issue(1, 1);

    int st = 0;
    for (int c = 0; c < nch; c++) {
        CP_WAIT1();
        __syncthreads();
        if (c + 2 < nch) {
            int stn = st + 2; if (stn >= STAGES) stn -= STAGES;
            issue(c + 2, stn);
        }

        const uint32_t Sa = sb + (uint32_t)st * STAGE;
#pragma unroll
        for (int i = 0; i < 4; i++) {
            const int ks = (i + ksoff) & 3;    // staggered phase per warp
            uint32_t ah[4][4];
#pragma unroll
            for (int mt = 0; mt < 4; mt++) {
                uint32_t sg = (uint32_t)(ks * 2 + asegh);
                uint32_t off = ar128[mt] + ((sg ^ axr[mt]) << 4);
                ldsm4(ah[mt][0], ah[mt][1], ah[mt][2], ah[mt][3], Sa + A_OFF + off);
            }
            uint32_t bh[4][2];
#pragma unroll
            for (int np = 0; np < 2; np++) {
                uint32_t sg = (uint32_t)(ks * 2 + bsegh);
                uint32_t off = br128[np] + ((sg ^ bxr[np]) << 4);
                uint32_t q0, q1, q2, q3;
                ldsm4(q0, q1, q2, q3, Sa + B_OFF + off);
                bh[np * 2][0] = q0; bh[np * 2][1] = q1;
                bh[np * 2 + 1][0] = q2; bh[np * 2 + 1][1] = q3;
            }
#pragma unroll
            for (int mt = 0; mt < 4; mt++)
#pragma unroll
                for (int nt = 0; nt < 4; nt++)
                    mma_f16(acc[mt][nt], ah[mt], bh[nt]);
        }
        st++; if (st >= STAGES) st = 0;
    }
    CP_WAIT0();

    // ---------------- epilogue ----------------
    if (OUT == 3) {
        __syncthreads();
        float* ts = (float*)smem;  // [128][TS_STRIDE]
        uint16_t* Co = Ch + bz * sC;
#pragma unroll
        for (int mt = 0; mt < 4; mt++) {
            const int rl = warpM * 64 + mt * 16 + (lane >> 2);
#pragma unroll
            for (int nt = 0; nt < 4; nt++) {
                const int cl = warpN * 32 + nt * 8 + (lane & 3) * 2;
                ts[cl * TS_STRIDE + rl]           = acc[mt][nt][0];
                ts[(cl + 1) * TS_STRIDE + rl]     = acc[mt][nt][1];
                ts[cl * TS_STRIDE + rl + 8]       = acc[mt][nt][2];
                ts[(cl + 1) * TS_STRIDE + rl + 8] = acc[mt][nt][3];
            }
        }
        __syncthreads();
        const int nr = t >> 1;               // 0..127
        const int mh = (t & 1) * 64;
        const float* src = ts + nr * TS_STRIDE + mh;
        const size_t rowb = (size_t)(n0 + nr) * ldc + m0 + mh;
#pragma unroll
        for (int i = 0; i < 64; i += 2)
            st_f16x2(Co, rowb + i, src[i], src[i + 1]);
        return;
    }

    float* Cfo = (OUT == 0) ? (Cf + bz * sC) : nullptr;
    uint16_t* Cho = (OUT != 0) ? (Ch + bz * sC) : nullptr;

#pragma unroll
    for (int mt = 0; mt < 4; mt++) {
        const int r0i = m0 + warpM * 64 + mt * 16 + (lane >> 2);
        float inv0 = 1.0f, inv1 = 1.0f;
        if (OUT == 6) {
            inv0 = 1.0f / aux[bz * sAux + r0i];
            inv1 = 1.0f / aux[bz * sAux + r0i + 8];
        }
        __half2 hs0 = __floats2half2_rn(0.0f, 0.0f);
        __half2 hs1 = __floats2half2_rn(0.0f, 0.0f);
#pragma unroll
        for (int nt = 0; nt < 4; nt++) {
            const int col = n0 + warpN * 32 + nt * 8 + (lane & 3) * 2;
            const size_t i0 = (size_t)r0i * ldc + col;
            const size_t i1 = (size_t)(r0i + 8) * ldc + col;
            float v0 = acc[mt][nt][0], v1 = acc[mt][nt][1];
            float v2 = acc[mt][nt][2], v3 = acc[mt][nt][3];
            if (OUT == 0) {
                float b0 = aux ? aux[col] : 0.0f;
                float b1 = aux ? aux[col + 1] : 0.0f;
                *(float2*)&Cfo[i0] = make_float2(v0 * alpha + b0, v1 * alpha + b1);
                *(float2*)&Cfo[i1] = make_float2(v2 * alpha + b0, v3 * alpha + b1);
            } else if (OUT == 2) {
                st_f16x2(Cho, i0, v0, v1);
                st_f16x2(Cho, i1, v2, v3);
            } else if (OUT == 5) {
                uint32_t e01 = ex2_f16x2(alpha * v0, alpha * v1);
                uint32_t e23 = ex2_f16x2(alpha * v2, alpha * v3);
                *(uint32_t*)(Cho + i0) = e01;
                *(uint32_t*)(Cho + i1) = e23;
                hs0 = __hadd2(hs0, *(__half2*)&e01);
                hs1 = __hadd2(hs1, *(__half2*)&e23);
            } else if (OUT == 6) {
                st_f16x2(Cho, i0, v0 * inv0, v1 * inv0);
                st_f16x2(Cho, i1, v2 * inv1, v3 * inv1);
            }
        }
        if (OUT == 5) {
            float s0 = __low2float(hs0) + __high2float(hs0);
            float s1 = __low2float(hs1) + __high2float(hs1);
            s0 += __shfl_xor_sync(0xffffffffu, s0, 1);
            s0 += __shfl_xor_sync(0xffffffffu, s0, 2);
            s1 += __shfl_xor_sync(0xffffffffu, s1, 1);
            s1 += __shfl_xor_sync(0xffffffffu, s1, 2);
            if ((lane & 3) == 0) {
                float* part = Cf + ((size_t)blockIdx.x * 4 + warpN) * MTOT
                                 + bz * sAux;
                part[r0i]     = s0;
                part[r0i + 8] = s1;
            }
        }
    }
}

// ---------------- converts ----------------------------------------------------

__global__ void convert_xy(const float4* __restrict__ x,
                           const float4* __restrict__ y,
                           uint32_t* __restrict__ xd,
                           uint32_t* __restrict__ yd, long n4)
{
    long i = (long)blockIdx.x * blockDim.x + threadIdx.x;
    const long stride = (long)gridDim.x * blockDim.x;
    for (; i < 2 * n4; i += stride) {
        const bool isY = (i >= n4);
        long j = isY ? i - n4 : i;
        float4 f = (isY ? y : x)[j];
        uint32_t* d = isY ? yd : xd;
        __half2 h0 = __floats2half2_rn(f.x, f.y);
        __half2 h1 = __floats2half2_rn(f.z, f.w);
        d[j * 2 + 0] = *(uint32_t*)&h0;
        d[j * 2 + 1] = *(uint32_t*)&h1;
    }
}

__global__ void convert_w4(const float4* __restrict__ wq,
                           const float4* __restrict__ wk,
                           const float4* __restrict__ wv,
                           const float4* __restrict__ wo,
                           uint32_t* __restrict__ wqk,
                           uint32_t* __restrict__ wvd,
                           uint32_t* __restrict__ wod)
{
    const long n4 = (long)DIM * DIM / 4;
    long i = (long)blockIdx.x * blockDim.x + threadIdx.x;
    const long stride = (long)gridDim.x * blockDim.x;
    for (; i < 4 * n4; i += stride) {
        int which = (int)(i / n4);
        long j = i - (long)which * n4;
        const float4* s = (which == 0) ? wq : (which == 1) ? wk
                        : (which == 2) ? wv : wo;
        uint32_t* d = (which == 0) ? wqk : (which == 1) ? (wqk + 2 * n4)
                    : (which == 2) ? wvd : wod;
        float4 f = s[j];
        __half2 h0 = __floats2half2_rn(f.x, f.y);
        __half2 h1 = __floats2half2_rn(f.z, f.w);
        d[j * 2 + 0] = *(uint32_t*)&h0;
        d[j * 2 + 1] = *(uint32_t*)&h1;
    }
}

// ---------------- fold per-(xblock,warpN) row-sum partials --------------------

__global__ __launch_bounds__(256) void reduce_rsum(
    const float* __restrict__ part, float* __restrict__ rsum)
{
    const int row = blockIdx.x * 256 + threadIdx.x;
    float s = 0.0f;
#pragma unroll 16
    for (int x = 0; x < NPARTS; x++)
        s += part[(size_t)x * MTOT + row];
    rsum[row] = s;
}

// ---------------- launch ------------------------------------------------------

extern "C" void kernel_launch(void* const* d_in, const int* in_sizes, int n_in,
                              void* d_out, int out_size)
{
    const float* x  = (const float*)d_in[0];
    const float* y  = (const float*)d_in[1];
    const float* Wq = (const float*)d_in[2];
    const float* Wk = (const float*)d_in[3];
    const float* Wv = (const float*)d_in[4];
    const float* Wo = (const float*)d_in[5];
    const float* bo = (const float*)d_in[6];
    float* out = (float*)d_out;

    auto sym = [](const void* s) {
        void* p = nullptr;
        cudaGetSymbolAddress(&p, (const void*)s);
        return p;
    };
    uint16_t* x16   = (uint16_t*)sym(g_x16);
    uint16_t* y16   = (uint16_t*)sym(g_y16);
    uint16_t* wqk16 = (uint16_t*)sym(g_wqk16);
    uint16_t* wv16  = (uint16_t*)sym(g_wv16);
    uint16_t* wo16  = (uint16_t*)sym(g_wo16);
    uint16_t* qk16  = (uint16_t*)sym(g_qk16);
    uint16_t* vt    = (uint16_t*)sym(g_vt);
    uint16_t* p     = (uint16_t*)sym(g_p);
    float*    rp    = (float*)sym(g_rpart);
    float*    rs    = (float*)sym(g_rsum);
    uint16_t* c16   = (uint16_t*)sym(g_c16);

    cudaFuncSetAttribute(gemm<0>, cudaFuncAttributeMaxDynamicSharedMemorySize, SMEM_MAIN);
    cudaFuncSetAttribute(gemm<2>, cudaFuncAttributeMaxDynamicSharedMemorySize, SMEM_MAIN);
    cudaFuncSetAttribute(gemm<3>, cudaFuncAttributeMaxDynamicSharedMemorySize, SMEM_MAIN);
    cudaFuncSetAttribute(gemm<5>, cudaFuncAttributeMaxDynamicSharedMemorySize, SMEM_MAIN);
    cudaFuncSetAttribute(gemm<6>, cudaFuncAttributeMaxDynamicSharedMemorySize, SMEM_MAIN);

    const float SCALE = 0.044194173824159216f;               // 1/sqrt(512)
    const float SCALE_LOG2E = SCALE * 1.4426950408889634f;   // fold log2(e)

    const long nXY4 = (long)MTOT * DIM / 4;

    // 0) convert inputs (x + y fused)
    convert_xy<<<4096, 256>>>((const float4*)x, (const float4*)y,
                              (uint32_t*)x16, (uint32_t*)y16, nXY4);
    // 1) convert all 4 weights (Wq|Wk concatenated)
    convert_w4<<<1024, 256>>>((const float4*)Wq, (const float4*)Wk,
                              (const float4*)Wv, (const float4*)Wo,
                              (uint32_t*)wqk16, (uint32_t*)wv16, (uint32_t*)wo16);

    // 2) fused Q|K projection: [16384,1024] = x16 @ Wqk^T  -> qk16 (ldc=1024)
    {
        dim3 grid(2 * DIM / BN, MTOT / BM, 1);
        gemm<2><<<grid, 256, SMEM_MAIN>>>(x16, wqk16, DIM, DIM, DIM, 0, 0,
                                          nullptr, qk16, 2 * DIM, 0,
                                          1.0f, nullptr, 0);
    }
    // 3) P_unnorm = 2^(SCALE_LOG2E * Q @ K^T) + row-sum partials  [profile target]
    {
        dim3 grid(SEQ / BN, SEQ / BM, BATCH);
        gemm<5><<<grid, 256, SMEM_MAIN>>>(qk16, qk16 + DIM, DIM,
                                          2 * DIM, 2 * DIM,
                                          (long)SEQ * 2 * DIM, (long)SEQ * 2 * DIM,
                                          rp, p, SEQ,
                                          (long)SEQ * SEQ, SCALE_LOG2E, nullptr, SEQ);
    }
    // 4) V projection -> fp16 transposed per batch: vt[b][d][seq]
    {
        dim3 grid(DIM / BN, SEQ / BM, BATCH);
        gemm<3><<<grid, 256, SMEM_MAIN>>>(y16, wv16, DIM, DIM, DIM,
                                          (long)SEQ * DIM, 0,
                                          nullptr, vt, SEQ,
                                          (long)DIM * SEQ, 1.0f, nullptr, 0);
    }
    // 5) fold row-sum partials
    reduce_rsum<<<MTOT / 256, 256>>>(rp, rs);
    // 6) Context: C = (P @ V) / rowsum -> fp16
    {
        dim3 grid(DIM / BN, SEQ / BM, BATCH);
        gemm<6><<<grid, 256, SMEM_MAIN>>>(p, vt, SEQ, SEQ, SEQ,
                                          (long)SEQ * SEQ, (long)DIM * SEQ,
                                          nullptr, c16, DIM,
                                          (long)SEQ * DIM, 1.0f, rs, SEQ);
    }
    // 7) Output projection + bias -> fp32
    {
        dim3 grid(DIM / BN, MTOT / BM, 1);
        gemm<0><<<grid, 256, SMEM_MAIN>>>(c16, wo16, DIM, DIM, DIM, 0, 0,
                                          out, nullptr, DIM, 0, 1.0f, bo, 0);
    }
}

// round 17
// speedup vs baseline: 1.1956x; 1.0214x over previous
#include <cuda_runtime.h>
#include <cuda_fp16.h>
#include <stdint.h>

// ---------------------------------------------------------------------------
// Multihead_Attention b=4, n=4096, d=512, inner=512
// R18: R12 core (verified 501us). QK^T gets a dedicated kernel: fp16
//      accumulators (acc 64->32 regs) buy double-buffered fragments with
//      cross-chunk ks0 prefetch at 2 CTAs/SM -- continuous MMA issue across
//      the chunk barrier. PV/projections unchanged (fp32 acc).
// ---------------------------------------------------------------------------

#define BATCH 4
#define SEQ   4096
#define DIM   512
#define MTOT  (BATCH * SEQ)

#define BM 128
#define BN 128
#define NPARTS 128   // (SEQ/BN)=32 x-blocks * 4 warpN partials

// scratch (fp16 storage as uint16)
__device__ uint16_t g_x16[(size_t)MTOT * DIM];
__device__ uint16_t g_y16[(size_t)MTOT * DIM];
__device__ uint16_t g_wqk16[2 * DIM * DIM];
__device__ uint16_t g_wv16[DIM * DIM];
__device__ uint16_t g_wo16[DIM * DIM];
__device__ uint16_t g_qk16[(size_t)MTOT * 2 * DIM];     // fused q|k, ld=1024
__device__ uint16_t g_vt [(size_t)BATCH * DIM * SEQ];   // V^T per batch [512,4096]
__device__ uint16_t g_p  [(size_t)BATCH * SEQ * SEQ];   // 2^(scaled logits), fp16
__device__ float    g_rpart[(size_t)NPARTS * MTOT];
__device__ float    g_rsum[MTOT];
__device__ uint16_t g_c16[(size_t)MTOT * DIM];

// ---------------- helpers ---------------------------------------------------

__device__ __forceinline__ uint32_t smem_u32(const void* p) {
    uint32_t a;
    asm("{ .reg .u64 t; cvta.to.shared.u64 t, %1; cvt.u32.u64 %0, t; }"
        : "=r"(a) : "l"(p));
    return a;
}

__device__ __forceinline__ void ldsm4(uint32_t& r0, uint32_t& r1,
                                      uint32_t& r2, uint32_t& r3, uint32_t a) {
    asm volatile("ldmatrix.sync.aligned.m8n8.x4.shared.b16 {%0,%1,%2,%3}, [%4];"
                 : "=r"(r0), "=r"(r1), "=r"(r2), "=r"(r3) : "r"(a));
}

__device__ __forceinline__ void mma_f16(float* d, const uint32_t* a,
                                        const uint32_t* b) {
    asm volatile(
        "mma.sync.aligned.m16n8k16.row.col.f32.f16.f16.f32 "
        "{%0,%1,%2,%3}, {%4,%5,%6,%7}, {%8,%9}, {%0,%1,%2,%3};"
        : "+f"(d[0]), "+f"(d[1]), "+f"(d[2]), "+f"(d[3])
        : "r"(a[0]), "r"(a[1]), "r"(a[2]), "r"(a[3]), "r"(b[0]), "r"(b[1]));
}

// fp16-accumulator variant: D,C are 2 regs (4 halves)
__device__ __forceinline__ void mma_f16h(uint32_t* d, const uint32_t* a,
                                         const uint32_t* b) {
    asm volatile(
        "mma.sync.aligned.m16n8k16.row.col.f16.f16.f16.f16 "
        "{%0,%1}, {%2,%3,%4,%5}, {%6,%7}, {%0,%1};"
        : "+r"(d[0]), "+r"(d[1])
        : "r"(a[0]), "r"(a[1]), "r"(a[2]), "r"(a[3]), "r"(b[0]), "r"(b[1]));
}

#define CP16(dst, src) \
    asm volatile("cp.async.cg.shared.global [%0], [%1], 16;" \
                 :: "r"(dst), "l"(src) : "memory")
#define CP_COMMIT() asm volatile("cp.async.commit_group;" ::: "memory")
#define CP_WAIT1()  asm volatile("cp.async.wait_group 1;" ::: "memory")
#define CP_WAIT0()  asm volatile("cp.async.wait_group 0;" ::: "memory")

__device__ __forceinline__ void st_f16x2(uint16_t* H, size_t idx,
                                         float v0, float v1) {
    __half2 h = __floats2half2_rn(v0, v1);
    *(uint32_t*)(H + idx) = *(uint32_t*)&h;
}

// f16x2 exp2: one MUFU op for two values
__device__ __forceinline__ uint32_t ex2_f16x2_h(__half2 hx) {
    uint32_t hin = *(uint32_t*)&hx;
    uint32_t hout;
    asm volatile("ex2.approx.f16x2 %0, %1;" : "=r"(hout) : "r"(hin));
    return hout;
}

// ---------------- shared tile constants ---------------------------------------
#define TS_STRIDE 132
#define STAGES 3
#define A_OFF  0u
#define B_OFF  16384u
#define STAGE  32768u
#define SMEM_MAIN (STAGES * 32768)            // 98304

// ---------------- GEMM (R12): projections + PV ---------------------------------
// C = A[M,K](f16, lda) @ B[N,K]^T(f16, ldb), fp32 accum. CTA 128x128, warp 64x32.
// OUT: 0 = fp32 * alpha + bias(aux); 2 = f16; 3 = f16 transposed;
//      6 = f16 of acc / aux[bz*sAux + row]

template <int OUT>
__global__ __launch_bounds__(256, 2) void gemm(
    const uint16_t* __restrict__ A, const uint16_t* __restrict__ B,
    int K, int lda, int ldb, long sA, long sB,
    float* __restrict__ Cf, uint16_t* __restrict__ Ch,
    int ldc, long sC, float alpha,
    const float* __restrict__ aux, long sAux)
{
    extern __shared__ char smem[];
    const uint32_t sb = smem_u32(smem);
    const int t = threadIdx.x, lane = t & 31, wid = t >> 5;
    const int warpM = wid & 1;
    const int warpN = wid >> 1;

    const int bz = blockIdx.z;
    A += bz * sA; B += bz * sB;
    const int m0 = blockIdx.y * BM, n0 = blockIdx.x * BN;

    const int seg = t & 7;
    const int r0  = t >> 3;
    const uint32_t dA = (uint32_t)r0 * 128u
                      + (((uint32_t)seg ^ ((uint32_t)r0 & 7u)) << 4);
    const long rowStepA = (long)32 * lda;
    const long rowStepB = (long)32 * ldb;

    const uint16_t* srcA = A + (long)(m0 + r0) * lda + seg * 8;
    const uint16_t* srcB = B + (long)(n0 + r0) * ldb + seg * 8;

    const int arow_o = warpM * 64 + (lane & 7) + ((lane >> 3) & 1) * 8;
    const int asegh  = lane >> 4;
    const int brow_o = warpN * 32 + (lane & 7) + (lane >> 4) * 8;
    const int bsegh  = (lane >> 3) & 1;

    uint32_t ar128[4], axr[4];
#pragma unroll
    for (int mt = 0; mt < 4; mt++) {
        int r = arow_o + mt * 16;
        ar128[mt] = (uint32_t)(r * 128);
        axr[mt]   = (uint32_t)(r & 7);
    }
    uint32_t br128[2], bxr[2];
#pragma unroll
    for (int np = 0; np < 2; np++) {
        int r = brow_o + np * 16;
        br128[np] = (uint32_t)(r * 128);
        bxr[np]   = (uint32_t)(r & 7);
    }

    float acc[4][4][4];
#pragma unroll
    for (int i = 0; i < 4; i++)
#pragma unroll
        for (int j = 0; j < 4; j++)
#pragma unroll
            for (int k = 0; k < 4; k++) acc[i][j][k] = 0.0f;

    const int nch = K >> 6;

    auto issue = [&](int c, int st) {
        const uint32_t base = sb + (uint32_t)st * STAGE;
        const uint16_t* pa = srcA + c * 64;
        const uint16_t* pb = srcB + c * 64;
#pragma unroll
        for (int i = 0; i < 4; i++) {
            CP16(base + A_OFF + dA + i * 4096u, pa + i * rowStepA);
            CP16(base + B_OFF + dA + i * 4096u, pb + i * rowStepB);
        }
        CP_COMMIT();
    };

    issue(0, 0);
    issue(1, 1);

    int st = 0;
    for (int c = 0; c < nch; c++) {
        CP_WAIT1();
        __syncthreads();
        if (c + 2 < nch) {
            int stn = st + 2; if (stn >= STAGES) stn -= STAGES;
            issue(c + 2, stn);
        }

        const uint32_t Sa = sb + (uint32_t)st * STAGE;
#pragma unroll
        for (int ks = 0; ks < 4; ks++) {
            uint32_t ah[4][4];
#pragma unroll
            for (int mt = 0; mt < 4; mt++) {
                uint32_t sg = (uint32_t)(ks * 2 + asegh);
                uint32_t off = ar128[mt] + ((sg ^ axr[mt]) << 4);
                ldsm4(ah[mt][0], ah[mt][1], ah[mt][2], ah[mt][3], Sa + A_OFF + off);
            }
            uint32_t bh[4][2];
#pragma unroll
            for (int np = 0; np < 2; np++) {
                uint32_t sg = (uint32_t)(ks * 2 + bsegh);
                uint32_t off = br128[np] + ((sg ^ bxr[np]) << 4);
                uint32_t q0, q1, q2, q3;
                ldsm4(q0, q1, q2, q3, Sa + B_OFF + off);
                bh[np * 2][0] = q0; bh[np * 2][1] = q1;
                bh[np * 2 + 1][0] = q2; bh[np * 2 + 1][1] = q3;
            }
#pragma unroll
            for (int mt = 0; mt < 4; mt++)
#pragma unroll
                for (int nt = 0; nt < 4; nt++)
                    mma_f16(acc[mt][nt], ah[mt], bh[nt]);
        }
        st++; if (st >= STAGES) st = 0;
    }
    CP_WAIT0();

    // ---------------- epilogue ----------------
    if (OUT == 3) {
        __syncthreads();
        float* ts = (float*)smem;  // [128][TS_STRIDE]
        uint16_t* Co = Ch + bz * sC;
#pragma unroll
        for (int mt = 0; mt < 4; mt++) {
            const int rl = warpM * 64 + mt * 16 + (lane >> 2);
#pragma unroll
            for (int nt = 0; nt < 4; nt++) {
                const int cl = warpN * 32 + nt * 8 + (lane & 3) * 2;
                ts[cl * TS_STRIDE + rl]           = acc[mt][nt][0];
                ts[(cl + 1) * TS_STRIDE + rl]     = acc[mt][nt][1];
                ts[cl * TS_STRIDE + rl + 8]       = acc[mt][nt][2];
                ts[(cl + 1) * TS_STRIDE + rl + 8] = acc[mt][nt][3];
            }
        }
        __syncthreads();
        const int nr = t >> 1;
        const int mh = (t & 1) * 64;
        const float* src = ts + nr * TS_STRIDE + mh;
        const size_t rowb = (size_t)(n0 + nr) * ldc + m0 + mh;
#pragma unroll
        for (int i = 0; i < 64; i += 2)
            st_f16x2(Co, rowb + i, src[i], src[i + 1]);
        return;
    }

    float* Cfo = (OUT == 0) ? (Cf + bz * sC) : nullptr;
    uint16_t* Cho = (OUT != 0) ? (Ch + bz * sC) : nullptr;

#pragma unroll
    for (int mt = 0; mt < 4; mt++) {
        const int r0i = m0 + warpM * 64 + mt * 16 + (lane >> 2);
        float inv0 = 1.0f, inv1 = 1.0f;
        if (OUT == 6) {
            inv0 = 1.0f / aux[bz * sAux + r0i];
            inv1 = 1.0f / aux[bz * sAux + r0i + 8];
        }
#pragma unroll
        for (int nt = 0; nt < 4; nt++) {
            const int col = n0 + warpN * 32 + nt * 8 + (lane & 3) * 2;
            const size_t i0 = (size_t)r0i * ldc + col;
            const size_t i1 = (size_t)(r0i + 8) * ldc + col;
            float v0 = acc[mt][nt][0], v1 = acc[mt][nt][1];
            float v2 = acc[mt][nt][2], v3 = acc[mt][nt][3];
            if (OUT == 0) {
                float b0 = aux ? aux[col] : 0.0f;
                float b1 = aux ? aux[col + 1] : 0.0f;
                *(float2*)&Cfo[i0] = make_float2(v0 * alpha + b0, v1 * alpha + b1);
                *(float2*)&Cfo[i1] = make_float2(v2 * alpha + b0, v3 * alpha + b1);
            } else if (OUT == 2) {
                st_f16x2(Cho, i0, v0, v1);
                st_f16x2(Cho, i1, v2, v3);
            } else if (OUT == 6) {
                st_f16x2(Cho, i0, v0 * inv0, v1 * inv0);
                st_f16x2(Cho, i1, v2 * inv1, v3 * inv1);
            }
        }
    }
}

// ---------------- GEMM_QK: fp16 acc + cross-chunk fragment prefetch -----------
// P = 2^(alpha * Q@K^T) in f16, + per-(xblock,warpN) row-sum partials.
// 2 CTAs/SM (regs ~115 via f16 acc).

__global__ __launch_bounds__(256, 2) void gemm_qk(
    const uint16_t* __restrict__ A, const uint16_t* __restrict__ B,
    int K, int lda, int ldb, long sA, long sB,
    float* __restrict__ Cf, uint16_t* __restrict__ Ch,
    int ldc, long sC, float alpha, long sAux)
{
    extern __shared__ char smem[];
    const uint32_t sb = smem_u32(smem);
    const int t = threadIdx.x, lane = t & 31, wid = t >> 5;
    const int warpM = wid & 1;
    const int warpN = wid >> 1;

    const int bz = blockIdx.z;
    A += bz * sA; B += bz * sB;
    const int m0 = blockIdx.y * BM, n0 = blockIdx.x * BN;

    const int seg = t & 7;
    const int r0  = t >> 3;
    const uint32_t dA = (uint32_t)r0 * 128u
                      + (((uint32_t)seg ^ ((uint32_t)r0 & 7u)) << 4);
    const long rowStepA = (long)32 * lda;
    const long rowStepB = (long)32 * ldb;

    const uint16_t* srcA = A + (long)(m0 + r0) * lda + seg * 8;
    const uint16_t* srcB = B + (long)(n0 + r0) * ldb + seg * 8;

    const int arow_o = warpM * 64 + (lane & 7) + ((lane >> 3) & 1) * 8;
    const int asegh  = lane >> 4;
    const int brow_o = warpN * 32 + (lane & 7) + (lane >> 4) * 8;
    const int bsegh  = (lane >> 3) & 1;

    uint32_t ar128[4], axr[4];
#pragma unroll
    for (int mt = 0; mt < 4; mt++) {
        int r = arow_o + mt * 16;
        ar128[mt] = (uint32_t)(r * 128);
        axr[mt]   = (uint32_t)(r & 7);
    }
    uint32_t br128[2], bxr[2];
#pragma unroll
    for (int np = 0; np < 2; np++) {
        int r = brow_o + np * 16;
        br128[np] = (uint32_t)(r * 128);
        bxr[np]   = (uint32_t)(r & 7);
    }

    // fp16 accumulators: 4x4 tiles x 2 regs
    uint32_t acc[4][4][2];
#pragma unroll
    for (int i = 0; i < 4; i++)
#pragma unroll
        for (int j = 0; j < 4; j++) { acc[i][j][0] = 0u; acc[i][j][1] = 0u; }

    const int nch = K >> 6;

    auto issue = [&](int c, int st) {
        const uint32_t base = sb + (uint32_t)st * STAGE;
        const uint16_t* pa = srcA + c * 64;
        const uint16_t* pb = srcB + c * 64;
#pragma unroll
        for (int i = 0; i < 4; i++) {
            CP16(base + A_OFF + dA + i * 4096u, pa + i * rowStepA);
            CP16(base + B_OFF + dA + i * 4096u, pb + i * rowStepB);
        }
        CP_COMMIT();
    };

    // fragment double buffers
    uint32_t ah[2][4][4];
    uint32_t bh[2][4][2];

    auto loadFrag = [&](uint32_t Sa, int ks, int buf) {
#pragma unroll
        for (int mt = 0; mt < 4; mt++) {
            uint32_t sg = (uint32_t)(ks * 2 + asegh);
            uint32_t off = ar128[mt] + ((sg ^ axr[mt]) << 4);
            ldsm4(ah[buf][mt][0], ah[buf][mt][1], ah[buf][mt][2], ah[buf][mt][3],
                  Sa + A_OFF + off);
        }
#pragma unroll
        for (int np = 0; np < 2; np++) {
            uint32_t sg = (uint32_t)(ks * 2 + bsegh);
            uint32_t off = br128[np] + ((sg ^ bxr[np]) << 4);
            uint32_t q0, q1, q2, q3;
            ldsm4(q0, q1, q2, q3, Sa + B_OFF + off);
            bh[buf][np * 2][0] = q0; bh[buf][np * 2][1] = q1;
            bh[buf][np * 2 + 1][0] = q2; bh[buf][np * 2 + 1][1] = q3;
        }
    };

    issue(0, 0);
    issue(1, 1);
    CP_WAIT1();                 // group 0 complete
    __syncthreads();
    loadFrag(sb, 0, 0);         // chunk 0, ks 0 -> buf 0

    int st = 0;
    int buf = 0;
    for (int c = 0; c < nch; c++) {
        // overwrite stage (c+2)%3 = (c-1)%3 — protected by end-of-chunk barrier
        if (c + 2 < nch) {
            int stn = st + 2; if (stn >= STAGES) stn -= STAGES;
            issue(c + 2, stn);
        }
        CP_WAIT1();             // chunks c and c+1 data complete

        const uint32_t Sa = sb + (uint32_t)st * STAGE;
        const uint32_t Sn = sb + (uint32_t)((st + 1 < STAGES) ? st + 1 : 0) * STAGE;
#pragma unroll
        for (int ks = 0; ks < 4; ks++) {
            const int cur = buf;
            const int nxt = buf ^ 1;
            if (ks < 3) {
                loadFrag(Sa, ks + 1, nxt);           // same-chunk prefetch
            } else if (c + 1 < nch) {
                loadFrag(Sn, 0, nxt);                // cross-chunk ks0 prefetch
            }
#pragma unroll
            for (int mt = 0; mt < 4; mt++)
#pragma unroll
                for (int nt = 0; nt < 4; nt++)
                    mma_f16h(acc[mt][nt], ah[cur][mt], bh[cur][nt]);
            buf ^= 1;
        }
        __syncthreads();        // all warps done reading stage c (and its frags)
        st++; if (st >= STAGES) st = 0;
    }
    CP_WAIT0();

    // ---------------- epilogue: exp + rowsum partials ----------------
    uint16_t* Cho = Ch + bz * sC;
    const __half2 alph2 = __float2half2_rn(alpha);

#pragma unroll
    for (int mt = 0; mt < 4; mt++) {
        const int r0i = m0 + warpM * 64 + mt * 16 + (lane >> 2);
        __half2 hs0 = __floats2half2_rn(0.0f, 0.0f);
        __half2 hs1 = __floats2half2_rn(0.0f, 0.0f);
#pragma unroll
        for (int nt = 0; nt < 4; nt++) {
            const int col = n0 + warpN * 32 + nt * 8 + (lane & 3) * 2;
            const size_t i0 = (size_t)r0i * ldc + col;
            const size_t i1 = (size_t)(r0i + 8) * ldc + col;
            __half2 h0 = *(__half2*)&acc[mt][nt][0];   // {v0, v1}
            __half2 h1 = *(__half2*)&acc[mt][nt][1];   // {v2, v3}
            uint32_t e01 = ex2_f16x2_h(__hmul2(h0, alph2));
            uint32_t e23 = ex2_f16x2_h(__hmul2(h1, alph2));
            *(uint32_t*)(Cho + i0) = e01;
            *(uint32_t*)(Cho + i1) = e23;
            hs0 = __hadd2(hs0, *(__half2*)&e01);
            hs1 = __hadd2(hs1, *(__half2*)&e23);
        }
        float s0 = __low2float(hs0) + __high2float(hs0);
        float s1 = __low2float(hs1) + __high2float(hs1);
        s0 += __shfl_xor_sync(0xffffffffu, s0, 1);
        s0 += __shfl_xor_sync(0xffffffffu, s0, 2);
        s1 += __shfl_xor_sync(0xffffffffu, s1, 1);
        s1 += __shfl_xor_sync(0xffffffffu, s1, 2);
        if ((lane & 3) == 0) {
            float* part = Cf + ((size_t)blockIdx.x * 4 + warpN) * MTOT
                             + bz * sAux;
            part[r0i]     = s0;
            part[r0i + 8] = s1;
        }
    }
}

// ---------------- converts ----------------------------------------------------

__global__ void convert_xy(const float4* __restrict__ x,
                           const float4* __restrict__ y,
                           uint32_t* __restrict__ xd,
                           uint32_t* __restrict__ yd, long n4)
{
    long i = (long)blockIdx.x * blockDim.x + threadIdx.x;
    const long stride = (long)gridDim.x * blockDim.x;
    for (; i < 2 * n4; i += stride) {
        const bool isY = (i >= n4);
        long j = isY ? i - n4 : i;
        float4 f = (isY ? y : x)[j];
        uint32_t* d = isY ? yd : xd;
        __half2 h0 = __floats2half2_rn(f.x, f.y);
        __half2 h1 = __floats2half2_rn(f.z, f.w);
        d[j * 2 + 0] = *(uint32_t*)&h0;
        d[j * 2 + 1] = *(uint32_t*)&h1;
    }
}

__global__ void convert_w4(const float4* __restrict__ wq,
                           const float4* __restrict__ wk,
                           const float4* __restrict__ wv,
                           const float4* __restrict__ wo,
                           uint32_t* __restrict__ wqk,
                           uint32_t* __restrict__ wvd,
                           uint32_t* __restrict__ wod)
{
    const long n4 = (long)DIM * DIM / 4;
    long i = (long)blockIdx.x * blockDim.x + threadIdx.x;
    const long stride = (long)gridDim.x * blockDim.x;
    for (; i < 4 * n4; i += stride) {
        int which = (int)(i / n4);
        long j = i - (long)which * n4;
        const float4* s = (which == 0) ? wq : (which == 1) ? wk
                        : (which == 2) ? wv : wo;
        uint32_t* d = (which == 0) ? wqk : (which == 1) ? (wqk + 2 * n4)
                    : (which == 2) ? wvd : wod;
        float4 f = s[j];
        __half2 h0 = __floats2half2_rn(f.x, f.y);
        __half2 h1 = __floats2half2_rn(f.z, f.w);
        d[j * 2 + 0] = *(uint32_t*)&h0;
        d[j * 2 + 1] = *(uint32_t*)&h1;
    }
}

// ---------------- fold per-(xblock,warpN) row-sum partials --------------------

__global__ __launch_bounds__(256) void reduce_rsum(
    const float* __restrict__ part, float* __restrict__ rsum)
{
    const int row = blockIdx.x * 256 + threadIdx.x;
    float s = 0.0f;
#pragma unroll 16
    for (int x = 0; x < NPARTS; x++)
        s += part[(size_t)x * MTOT + row];
    rsum[row] = s;
}

// ---------------- launch ------------------------------------------------------

extern "C" void kernel_launch(void* const* d_in, const int* in_sizes, int n_in,
                              void* d_out, int out_size)
{
    const float* x  = (const float*)d_in[0];
    const float* y  = (const float*)d_in[1];
    const float* Wq = (const float*)d_in[2];
    const float* Wk = (const float*)d_in[3];
    const float* Wv = (const float*)d_in[4];
    const float* Wo = (const float*)d_in[5];
    const float* bo = (const float*)d_in[6];
    float* out = (float*)d_out;

    auto sym = [](const void* s) {
        void* p = nullptr;
        cudaGetSymbolAddress(&p, (const void*)s);
        return p;
    };
    uint16_t* x16   = (uint16_t*)sym(g_x16);
    uint16_t* y16   = (uint16_t*)sym(g_y16);
    uint16_t* wqk16 = (uint16_t*)sym(g_wqk16);
    uint16_t* wv16  = (uint16_t*)sym(g_wv16);
    uint16_t* wo16  = (uint16_t*)sym(g_wo16);
    uint16_t* qk16  = (uint16_t*)sym(g_qk16);
    uint16_t* vt    = (uint16_t*)sym(g_vt);
    uint16_t* p     = (uint16_t*)sym(g_p);
    float*    rp    = (float*)sym(g_rpart);
    float*    rs    = (float*)sym(g_rsum);
    uint16_t* c16   = (uint16_t*)sym(g_c16);

    cudaFuncSetAttribute(gemm<0>, cudaFuncAttributeMaxDynamicSharedMemorySize, SMEM_MAIN);
    cudaFuncSetAttribute(gemm<2>, cudaFuncAttributeMaxDynamicSharedMemorySize, SMEM_MAIN);
    cudaFuncSetAttribute(gemm<3>, cudaFuncAttributeMaxDynamicSharedMemorySize, SMEM_MAIN);
    cudaFuncSetAttribute(gemm<6>, cudaFuncAttributeMaxDynamicSharedMemorySize, SMEM_MAIN);
    cudaFuncSetAttribute(gemm_qk, cudaFuncAttributeMaxDynamicSharedMemorySize, SMEM_MAIN);

    const float SCALE = 0.044194173824159216f;               // 1/sqrt(512)
    const float SCALE_LOG2E = SCALE * 1.4426950408889634f;   // fold log2(e)

    const long nXY4 = (long)MTOT * DIM / 4;

    // 0) convert inputs (x + y fused)
    convert_xy<<<4096, 256>>>((const float4*)x, (const float4*)y,
                              (uint32_t*)x16, (uint32_t*)y16, nXY4);
    // 1) convert all 4 weights (Wq|Wk concatenated)
    convert_w4<<<1024, 256>>>((const float4*)Wq, (const float4*)Wk,
                              (const float4*)Wv, (const float4*)Wo,
                              (uint32_t*)wqk16, (uint32_t*)wv16, (uint32_t*)wo16);

    // 2) fused Q|K projection: [16384,1024] = x16 @ Wqk^T  -> qk16 (ldc=1024)
    {
        dim3 grid(2 * DIM / BN, MTOT / BM, 1);
        gemm<2><<<grid, 256, SMEM_MAIN>>>(x16, wqk16, DIM, DIM, DIM, 0, 0,
                                          nullptr, qk16, 2 * DIM, 0,
                                          1.0f, nullptr, 0);
    }
    // 3) P_unnorm = 2^(SCALE_LOG2E * Q @ K^T) + row-sum partials  [profile target]
    {
        dim3 grid(SEQ / BN, SEQ / BM, BATCH);
        gemm_qk<<<grid, 256, SMEM_MAIN>>>(qk16, qk16 + DIM, DIM,
                                          2 * DIM, 2 * DIM,
                                          (long)SEQ * 2 * DIM, (long)SEQ * 2 * DIM,
                                          rp, p, SEQ,
                                          (long)SEQ * SEQ, SCALE_LOG2E, SEQ);
    }
    // 4) V projection -> fp16 transposed per batch: vt[b][d][seq]
    {
        dim3 grid(DIM / BN, SEQ / BM, BATCH);
        gemm<3><<<grid, 256, SMEM_MAIN>>>(y16, wv16, DIM, DIM, DIM,
                                          (long)SEQ * DIM, 0,
                                          nullptr, vt, SEQ,
                                          (long)DIM * SEQ, 1.0f, nullptr, 0);
    }
    // 5) fold row-sum partials
    reduce_rsum<<<MTOT / 256, 256>>>(rp, rs);
    // 6) Context: C = (P @ V) / rowsum -> fp16
    {
        dim3 grid(DIM / BN, SEQ / BM, BATCH);
        gemm<6><<<grid, 256, SMEM_MAIN>>>(p, vt, SEQ, SEQ, SEQ,
                                          (long)SEQ * SEQ, (long)DIM * SEQ,
                                          nullptr, c16, DIM,
                                          (long)SEQ * DIM, 1.0f, rs, SEQ);
    }
    // 7) Output projection + bias -> fp32
    {
        dim3 grid(DIM / BN, MTOT / BM, 1);
        gemm<0><<<grid, 256, SMEM_MAIN>>>(c16, wo16, DIM, DIM, DIM, 0, 0,
                                          out, nullptr, DIM, 0, 1.0f, bo, 0);
    }
}